// round 16
// baseline (speedup 1.0000x reference)
#include <cuda_runtime.h>
#include <math.h>
#include <stdint.h>

#define N_NODES 50000
#define F_IN    500
#define NEDGE   800000
#define MPAD    50048            // 391 * 128

// ---------------- scratch (device globals: no allocation allowed) ----------
__device__ __align__(256) float g_h  [N_NODES * 384];   // GEMM out (L0:384, L1:240)
__device__ __align__(256) float g_als[3 * N_NODES * 2];
__device__ __align__(256) float g_ald[3 * N_NODES * 2];
__device__ __align__(256) float g_s0 [N_NODES * 128];
__device__ __align__(256) float g_s1 [N_NODES * 128];
__device__ __align__(256) float g_s2 [N_NODES * 128];
__device__ __align__(256) float g_x  [N_NODES * 128];   // mix out / logits
__device__ __align__(256) float g_A2[(size_t)MPAD * 1024];  // split A (hi|lo), f32/tf32
__device__ __align__(256) float g_B2[384 * 1536];           // split B (hi|lo|hi)
__device__ int g_rowptr[3 * (N_NODES + 1)];
__device__ int g_csrc  [3][NEDGE];
__device__ int g_fill  [3 * N_NODES];

// ---------------- helpers ---------------------------------------------------
__device__ __forceinline__ float lrelu(float x) { return x > 0.f ? x : 0.2f * x; }
__device__ __forceinline__ float eluf (float x) { return x > 0.f ? x : expm1f(x); }

__device__ __forceinline__ uint32_t smem_to_u32(const void* p) {
    uint32_t a;
    asm("{ .reg .u64 t; cvta.to.shared.u64 t, %1; cvt.u32.u64 %0, t; }" : "=r"(a) : "l"(p));
    return a;
}
__device__ __forceinline__ float tf32_hi(float v) {
    uint32_t u;
    asm("cvt.rna.tf32.f32 %0, %1;" : "=r"(u) : "f"(v));
    return __uint_as_float(u);
}
__device__ __forceinline__ void ldsm_x4(uint32_t* r, uint32_t a) {
    asm volatile("ldmatrix.sync.aligned.m8n8.x4.shared.b16 {%0,%1,%2,%3}, [%4];"
                 : "=r"(r[0]), "=r"(r[1]), "=r"(r[2]), "=r"(r[3]) : "r"(a));
}
__device__ __forceinline__ void mma_tf32(float* c, const uint32_t* a, const uint32_t* b) {
    asm volatile("mma.sync.aligned.m16n8k8.row.col.f32.tf32.tf32.f32 "
                 "{%0,%1,%2,%3},{%4,%5,%6,%7},{%8,%9},{%0,%1,%2,%3};"
                 : "+f"(c[0]), "+f"(c[1]), "+f"(c[2]), "+f"(c[3])
                 : "r"(a[0]), "r"(a[1]), "r"(a[2]), "r"(a[3]), "r"(b[0]), "r"(b[1]));
}

// ---------------- split-tf32 conversion kernels ------------------------------
__global__ void k_cvtA(const float* __restrict__ X, float* __restrict__ A2,
                       int M, int K, int KHALF)
{
    long long i = (long long)blockIdx.x * blockDim.x + threadIdx.x;
    long long tot = (long long)MPAD * KHALF;
    if (i >= tot) return;
    int k = (int)(i % KHALF);
    long long row = i / KHALF;
    float v = (row < M && k < K) ? X[row * (long long)K + k] : 0.f;
    float hi = tf32_hi(v);
    A2[row * (2LL * KHALF) + k]         = hi;
    A2[row * (2LL * KHALF) + KHALF + k] = v - hi;
}

__global__ void k_cvtB(const float* W0, const float* W1, const float* W2,
                       float* __restrict__ B2, int K, int KHALF, int Np)
{
    int i = blockIdx.x * blockDim.x + threadIdx.x;
    int tot = 3 * Np * KHALF;
    if (i >= tot) return;
    int k = i % KHALF, n = i / KHALF;
    int o = n / Np, j = n % Np;
    const float* W = (o == 0) ? W0 : (o == 1) ? W1 : W2;
    float v = (k < K) ? W[(size_t)k * Np + j] : 0.f;
    float hi = tf32_hi(v);
    size_t base = (size_t)n * 3 * KHALF;
    B2[base + k]             = hi;
    B2[base + KHALF + k]     = v - hi;
    B2[base + 2 * KHALF + k] = hi;
}

// ---------------- tensor-core GEMM via tf32 mma.sync (3-term split) ---------
// C[M,NTOT] = A2 @ B2^T.  Block: 128 x BN, 8 warps (4m x 2n), K chunks of 32 f32,
// double-buffered SMEM with 144B row pitch (conflict-free ldmatrix + LDS).
template<int KHALF, int NTOT, int BN>
__global__ __launch_bounds__(256)
void tc_mma(const float* __restrict__ A2, const float* __restrict__ B2,
            float* __restrict__ C, int M)
{
    constexpr int CH     = KHALF / 32;
    constexpr int CHUNKS = 3 * CH;
    constexpr int ASTRB  = 2 * KHALF * 4;      // A2 row stride, bytes
    constexpr int BSTRB  = 3 * KHALF * 4;      // B2 row stride, bytes
    constexpr int LDT    = 144;                // smem row pitch, bytes (128 data + 16)
    constexpr int ABY    = 128 * LDT;
    constexpr int BBY    = BN * LDT;
    constexpr int STAGE  = ABY + BBY;
    constexpr int WN     = BN / 2;
    constexpr int NF     = WN / 8;
    constexpr int NVB    = BN * 8;             // B uint4 loads per chunk
    constexpr int BB     = (NVB + 255) / 256;

    extern __shared__ char smem[];
    const uint32_t sb = smem_to_u32(smem);
    const int tid = threadIdx.x, wid = tid >> 5, l = tid & 31;
    const int bm  = blockIdx.y * 128;
    const int bng = blockIdx.x * BN;
    const int warp_m = (wid & 3) * 32;
    const int warp_n = (wid >> 2) * WN;

    float acc[2][NF][4];
#pragma unroll
    for (int mf = 0; mf < 2; ++mf)
#pragma unroll
        for (int nf = 0; nf < NF; ++nf)
#pragma unroll
            for (int j = 0; j < 4; ++j) acc[mf][nf][j] = 0.f;

    // ldmatrix A base: lanes 0-7 rows 0-7 (f32 cols 0-3), 8-15 rows 8-15,
    // 16-23 rows 0-7 cols 4-7, 24-31 rows 8-15 cols 4-7  -> tf32 a-fragment.
    const int a_off = (warp_m + (l & 7) + ((l >> 3) & 1) * 8) * LDT + ((l >> 4) & 1) * 16;
    // B per-lane row base: n-row = warp_n + (l>>2), k-f32 = (l&3)
    const int b_row_off = (warp_n + (l >> 2)) * LDT + (l & 3) * 4;

#define LOADCH(c, ra, rb)                                                            \
    {                                                                                \
        const int aoff = ((c) < 2 * CH) ? ((c) % CH) * 32 : KHALF + ((c) - 2 * CH) * 32; \
        const char* Asrc = (const char*)(A2 + (size_t)bm * 2 * KHALF + aoff);        \
        _Pragma("unroll")                                                            \
        for (int i = 0; i < 4; ++i) {                                                \
            int idx = tid + i * 256;                                                 \
            int r = idx >> 3, q = idx & 7;                                           \
            ra[i] = *(const uint4*)(Asrc + (size_t)r * ASTRB + q * 16);              \
        }                                                                            \
        const char* Bsrc = (const char*)(B2 + (size_t)bng * 3 * KHALF + (c) * 32);   \
        _Pragma("unroll")                                                            \
        for (int i = 0; i < BB; ++i) {                                               \
            int idx = tid + i * 256;                                                 \
            if ((NVB % 256 == 0) || idx < NVB) {                                     \
                int n = idx >> 3, q = idx & 7;                                       \
                rb[i] = *(const uint4*)(Bsrc + (size_t)n * BSTRB + q * 16);          \
            }                                                                        \
        }                                                                            \
    }

#define STORECH(buf, ra, rb)                                                         \
    {                                                                                \
        char* ab = smem + (buf) * STAGE;                                             \
        char* bb = smem + (buf) * STAGE + ABY;                                       \
        _Pragma("unroll")                                                            \
        for (int i = 0; i < 4; ++i) {                                                \
            int idx = tid + i * 256;                                                 \
            int r = idx >> 3, q = idx & 7;                                           \
            *(uint4*)(ab + r * LDT + q * 16) = ra[i];                                \
        }                                                                            \
        _Pragma("unroll")                                                            \
        for (int i = 0; i < BB; ++i) {                                               \
            int idx = tid + i * 256;                                                 \
            if ((NVB % 256 == 0) || idx < NVB) {                                     \
                int n = idx >> 3, q = idx & 7;                                       \
                *(uint4*)(bb + n * LDT + q * 16) = rb[i];                            \
            }                                                                        \
        }                                                                            \
    }

#define COMPCH(buf)                                                                  \
    {                                                                                \
        const uint32_t aab = sb + (buf) * STAGE + a_off;                             \
        const uint32_t bbb = sb + (buf) * STAGE + ABY + b_row_off;                   \
        _Pragma("unroll")                                                            \
        for (int ks = 0; ks < 4; ++ks) {                                             \
            uint32_t a0[4], a1[4];                                                   \
            ldsm_x4(a0, aab + ks * 32);                                              \
            ldsm_x4(a1, aab + 16 * LDT + ks * 32);                                   \
            _Pragma("unroll")                                                        \
            for (int nf = 0; nf < NF; ++nf) {                                        \
                uint32_t b[2];                                                       \
                asm volatile("ld.shared.b32 %0, [%1];" : "=r"(b[0])                  \
                             : "r"(bbb + nf * 8 * LDT + ks * 32));                   \
                asm volatile("ld.shared.b32 %0, [%1];" : "=r"(b[1])                  \
                             : "r"(bbb + nf * 8 * LDT + ks * 32 + 16));              \
                mma_tf32(acc[0][nf], a0, b);                                         \
                mma_tf32(acc[1][nf], a1, b);                                         \
            }                                                                        \
        }                                                                            \
    }

    {
        uint4 ra[4], rb[BB];
        LOADCH(0, ra, rb);
        STORECH(0, ra, rb);
    }
    __syncthreads();
    for (int c = 1; c < CHUNKS; ++c) {
        uint4 ra[4], rb[BB];
        LOADCH(c, ra, rb);
        COMPCH((c - 1) & 1);
        STORECH(c & 1, ra, rb);
        __syncthreads();
    }
    COMPCH((CHUNKS - 1) & 1);

    // epilogue: fragment -> C
#pragma unroll
    for (int mf = 0; mf < 2; ++mf)
#pragma unroll
        for (int nf = 0; nf < NF; ++nf) {
            int r0  = bm + warp_m + mf * 16 + (l >> 2);
            int col = bng + warp_n + nf * 8 + (l & 3) * 2;
            if (r0 < M)
                *(float2*)(C + (size_t)r0 * NTOT + col) = make_float2(acc[mf][nf][0], acc[mf][nf][1]);
            int r1 = r0 + 8;
            if (r1 < M)
                *(float2*)(C + (size_t)r1 * NTOT + col) = make_float2(acc[mf][nf][2], acc[mf][nf][3]);
        }
#undef LOADCH
#undef STORECH
#undef COMPCH
}

// ---------------- fused attention logit pre-reduction over 3 orders ---------
__global__ void k_al3(const float* __restrict__ h, int RS, int C,
                      const float* as0, const float* as1, const float* as2,
                      const float* ad0, const float* ad1, const float* ad2,
                      float* __restrict__ als, float* __restrict__ ald)
{
    int w = (blockIdx.x * blockDim.x + threadIdx.x) >> 5;
    if (w >= N_NODES) return;
    int lane = threadIdx.x & 31;
    const float* row = h + (size_t)w * RS;
#pragma unroll
    for (int o = 0; o < 3; ++o) {
        const float* A_s = (o == 0) ? as0 : (o == 1) ? as1 : as2;
        const float* A_d = (o == 0) ? ad0 : (o == 1) ? ad1 : ad2;
#pragma unroll
        for (int hh = 0; hh < 2; ++hh) {
            float ss = 0.f, sd = 0.f;
            for (int c = lane; c < C; c += 32) {
                float v = row[o * 2 * C + hh * C + c];
                ss += v * __ldg(A_s + hh * C + c);
                sd += v * __ldg(A_d + hh * C + c);
            }
#pragma unroll
            for (int off = 16; off; off >>= 1) {
                ss += __shfl_xor_sync(~0u, ss, off);
                sd += __shfl_xor_sync(~0u, sd, off);
            }
            if (!lane) {
                als[o * 2 * N_NODES + w * 2 + hh] = ss;
                ald[o * 2 * N_NODES + w * 2 + hh] = sd;
            }
        }
    }
}

// ---------------- fused GAT aggregation: online softmax, batched prefetch ---
__global__ void k_gat3(const float* __restrict__ hall, int RS, int C,
                       const int* __restrict__ rowptr_all, const int* __restrict__ csrc_all,
                       const float* __restrict__ als_all, const float* __restrict__ ald_all,
                       const float* b0f, const float* b1f, const float* b2f,
                       float* o0, float* o1, float* o2, int concat)
{
    int n = (blockIdx.x * blockDim.x + threadIdx.x) >> 5;
    if (n >= N_NODES) return;
    const int o = blockIdx.y;
    const int* rowptr = rowptr_all + o * (N_NODES + 1);
    const int* csrc   = csrc_all + (size_t)o * NEDGE;
    const float* als  = als_all + o * 2 * N_NODES;
    const float* ald  = ald_all + o * 2 * N_NODES;
    const float* bias = (o == 0) ? b0f : (o == 1) ? b1f : b2f;
    float* out        = (o == 0) ? o0  : (o == 1) ? o1  : o2;
    const float* h    = hall + o * 2 * C;

    const int lane = threadIdx.x & 31;
    const int HC   = 2 * C;
    const int idx  = lane * 4;
    const bool act = idx < HC;
    const int head = (idx >= C) ? 1 : 0;

    const float adh = ald[n * 2 + head];
    float m   = lrelu(als[n * 2 + head] + adh);
    float den = 1.f;
    float4 acc = make_float4(0.f, 0.f, 0.f, 0.f);
    if (act) acc = *reinterpret_cast<const float4*>(h + (size_t)n * RS + idx);

    const int p0 = rowptr[n], p1 = rowptr[n + 1];
    for (int p = p0; p < p1; p += 8) {
        int sv[8]; float ev[8]; float4 hv[8];
#pragma unroll
        for (int i = 0; i < 8; ++i) {
            int q = p + i;
            sv[i] = csrc[q < p1 ? q : p1 - 1];
        }
#pragma unroll
        for (int i = 0; i < 8; ++i) ev[i] = als[sv[i] * 2 + head];
        if (act) {
#pragma unroll
            for (int i = 0; i < 8; ++i)
                hv[i] = *reinterpret_cast<const float4*>(h + (size_t)sv[i] * RS + idx);
        }
        const int cnt = min(8, p1 - p);
#pragma unroll
        for (int i = 0; i < 8; ++i) {
            if (i < cnt) {
                float e  = lrelu(ev[i] + adh);
                float nm = fmaxf(m, e);
                float sc = __expf(m - nm);
                float wg = __expf(e - nm);
                den = den * sc + wg;
                m = nm;
                if (act) {
                    acc.x = fmaf(acc.x, sc, wg * hv[i].x);
                    acc.y = fmaf(acc.y, sc, wg * hv[i].y);
                    acc.z = fmaf(acc.z, sc, wg * hv[i].z);
                    acc.w = fmaf(acc.w, sc, wg * hv[i].w);
                }
            }
        }
    }
    float inv = 1.f / (den + 1e-16f);
    float4 v = make_float4(acc.x * inv, acc.y * inv, acc.z * inv, acc.w * inv);

    if (concat) {
        if (act) {
            const float4 b = *reinterpret_cast<const float4*>(bias + idx);
            float4 r;
            r.x = eluf(v.x + b.x); r.y = eluf(v.y + b.y);
            r.z = eluf(v.z + b.z); r.w = eluf(v.w + b.w);
            *reinterpret_cast<float4*>(out + (size_t)n * HC + idx) = r;
        }
    } else {
        int half = C / 4;
        float ox = __shfl_down_sync(~0u, v.x, half);
        float oy = __shfl_down_sync(~0u, v.y, half);
        float oz = __shfl_down_sync(~0u, v.z, half);
        float ow = __shfl_down_sync(~0u, v.w, half);
        if (idx < C) {
            const float4 b = *reinterpret_cast<const float4*>(bias + idx);
            float4 r;
            r.x = eluf(0.5f * (v.x + ox) + b.x);
            r.y = eluf(0.5f * (v.y + oy) + b.y);
            r.z = eluf(0.5f * (v.z + oz) + b.z);
            r.w = eluf(0.5f * (v.w + ow) + b.w);
            *reinterpret_cast<float4*>(out + (size_t)n * C + idx) = r;
        }
    }
}

// ---------------- order mixing ----------------------------------------------
__global__ void k_mix(const float* __restrict__ s0, const float* __restrict__ s1,
                      const float* __restrict__ s2, const float* __restrict__ Wm,
                      const float* __restrict__ wf, float* __restrict__ out, int NC)
{
    int i = blockIdx.x * blockDim.x + threadIdx.x;
    if (i >= NC) return;
    float a = s0[i], b = s1[i], c = s2[i];
    float m0 = eluf(a * __ldg(Wm + 0) + b * __ldg(Wm + 3) + c * __ldg(Wm + 6));
    float m1 = eluf(a * __ldg(Wm + 1) + b * __ldg(Wm + 4) + c * __ldg(Wm + 7));
    float m2 = eluf(a * __ldg(Wm + 2) + b * __ldg(Wm + 5) + c * __ldg(Wm + 8));
    out[i] = m0 * __ldg(wf + 0) + m1 * __ldg(wf + 1) + m2 * __ldg(wf + 2);
}

// ---------------- row log-softmax over 40 classes ---------------------------
__global__ void k_lsm(const float* __restrict__ x, float* __restrict__ out)
{
    int n = (blockIdx.x * blockDim.x + threadIdx.x) >> 5;
    if (n >= N_NODES) return;
    int lane = threadIdx.x & 31;
    float v0 = (lane < 40)      ? x[(size_t)n * 40 + lane]      : -1e30f;
    float v1 = (lane + 32 < 40) ? x[(size_t)n * 40 + lane + 32] : -1e30f;
    float mx = fmaxf(v0, v1);
#pragma unroll
    for (int o = 16; o; o >>= 1) mx = fmaxf(mx, __shfl_xor_sync(~0u, mx, o));
    float s = 0.f;
    if (lane < 40)      s += expf(v0 - mx);
    if (lane + 32 < 40) s += expf(v1 - mx);
#pragma unroll
    for (int o = 16; o; o >>= 1) s += __shfl_xor_sync(~0u, s, o);
    float lse = logf(s) + mx;
    if (lane < 40)      out[(size_t)n * 40 + lane]      = v0 - lse;
    if (lane + 32 < 40) out[(size_t)n * 40 + lane + 32] = v1 - lse;
}

// ---------------- CSR build --------------------------------------------------
__global__ void k_zero2(int* a, int na, int* b, int nb)
{
    int i = blockIdx.x * blockDim.x + threadIdx.x;
    if (i < na) a[i] = 0;
    else if (i - na < nb) b[i - na] = 0;
}

__global__ void k_count3(const int* e0, const int* e1, const int* e2,
                         int* __restrict__ rowptr_all)
{
    int o = blockIdx.y;
    const int* ei = (o == 0) ? e0 : (o == 1) ? e1 : e2;
    int i = blockIdx.x * blockDim.x + threadIdx.x;
    if (i < NEDGE) atomicAdd(&rowptr_all[o * (N_NODES + 1) + ei[NEDGE + i] + 1], 1);
}

__global__ void k_scan3(int* __restrict__ rowptr_all)
{
    int* a = rowptr_all + blockIdx.x * (N_NODES + 1);
    const int n = N_NODES + 1;
    __shared__ int wsum[32];
    __shared__ int carry;
    int tid = threadIdx.x, lane = tid & 31, wid = tid >> 5;
    if (tid == 0) carry = 0;
    __syncthreads();
    for (int base = 0; base < n; base += 1024) {
        int i = base + tid;
        int v = (i < n) ? a[i] : 0;
#pragma unroll
        for (int off = 1; off < 32; off <<= 1) {
            int t = __shfl_up_sync(~0u, v, off);
            if (lane >= off) v += t;
        }
        if (lane == 31) wsum[wid] = v;
        __syncthreads();
        if (wid == 0) {
            int w = wsum[lane];
#pragma unroll
            for (int off = 1; off < 32; off <<= 1) {
                int t = __shfl_up_sync(~0u, w, off);
                if (lane >= off) w += t;
            }
            wsum[lane] = w;
        }
        __syncthreads();
        int add = carry + (wid ? wsum[wid - 1] : 0);
        if (i < n) a[i] = v + add;
        __syncthreads();
        if (tid == 0) carry += wsum[31];
        __syncthreads();
    }
}

__global__ void k_fill3(const int* e0, const int* e1, const int* e2,
                        const int* __restrict__ rowptr_all, int* __restrict__ fill,
                        int* __restrict__ csrc_all)
{
    int o = blockIdx.y;
    const int* ei = (o == 0) ? e0 : (o == 1) ? e1 : e2;
    int i = blockIdx.x * blockDim.x + threadIdx.x;
    if (i < NEDGE) {
        int d = ei[NEDGE + i];
        int pos = rowptr_all[o * (N_NODES + 1) + d] + atomicAdd(&fill[o * N_NODES + d], 1);
        csrc_all[(size_t)o * NEDGE + pos] = ei[i];
    }
}

// ---------------- host driver ------------------------------------------------
extern "C" void kernel_launch(void* const* d_in, const int* in_sizes, int n_in,
                              void* d_out, int out_size)
{
    (void)in_sizes; (void)n_in; (void)out_size;
    const float* x0 = (const float*)d_in[0];
    const int* e0 = (const int*)d_in[1];
    const int* e1 = (const int*)d_in[2];
    const int* e2 = (const int*)d_in[3];
    const float *W0[3], *as0[3], *ad0[3], *b0[3], *W1[3], *as1[3], *ad1[3], *b1[3];
    for (int o = 0; o < 3; ++o) {
        W0[o]  = (const float*)d_in[4  + 4 * o];
        as0[o] = (const float*)d_in[5  + 4 * o];
        ad0[o] = (const float*)d_in[6  + 4 * o];
        b0[o]  = (const float*)d_in[7  + 4 * o];
        W1[o]  = (const float*)d_in[16 + 4 * o];
        as1[o] = (const float*)d_in[17 + 4 * o];
        ad1[o] = (const float*)d_in[18 + 4 * o];
        b1[o]  = (const float*)d_in[19 + 4 * o];
    }
    const float* aggW0 = (const float*)d_in[28];
    const float* aggw0 = (const float*)d_in[29];
    const float* aggW1 = (const float*)d_in[30];
    const float* aggw1 = (const float*)d_in[31];

    float *h, *als, *ald, *st[3], *xb, *A2, *B2;
    int *rowptr, *csrc, *fill;
    {
        void* p;
        cudaGetSymbolAddress(&p, g_h);      h      = (float*)p;
        cudaGetSymbolAddress(&p, g_als);    als    = (float*)p;
        cudaGetSymbolAddress(&p, g_ald);    ald    = (float*)p;
        cudaGetSymbolAddress(&p, g_s0);     st[0]  = (float*)p;
        cudaGetSymbolAddress(&p, g_s1);     st[1]  = (float*)p;
        cudaGetSymbolAddress(&p, g_s2);     st[2]  = (float*)p;
        cudaGetSymbolAddress(&p, g_x);      xb     = (float*)p;
        cudaGetSymbolAddress(&p, g_A2);     A2     = (float*)p;
        cudaGetSymbolAddress(&p, g_B2);     B2     = (float*)p;
        cudaGetSymbolAddress(&p, g_rowptr); rowptr = (int*)p;
        cudaGetSymbolAddress(&p, g_csrc);   csrc   = (int*)p;
        cudaGetSymbolAddress(&p, g_fill);   fill   = (int*)p;
    }

    // smem: 2 stages of (128 + BN) rows * 144B
    const int SM0 = 2 * (128 + 128) * 144;   // 73728
    const int SM1 = 2 * (128 + 80) * 144;    // 59904
    cudaFuncSetAttribute(tc_mma<512, 384, 128>, cudaFuncAttributeMaxDynamicSharedMemorySize, SM0);
    cudaFuncSetAttribute(tc_mma<128, 240,  80>, cudaFuncAttributeMaxDynamicSharedMemorySize, SM1);

    const int TB  = 256;
    const int ebl = (NEDGE + TB - 1) / TB;
    const int nwb = (N_NODES * 32 + TB - 1) / TB;
    const int gwb = (N_NODES * 32 / 256);
    const int rb  = MPAD / 128;   // 391

    // 0-2: CSR count+scan (fill deferred so launch #5 = tc_mma for ncu -s 5)
    int na = 3 * (N_NODES + 1), nb = 3 * N_NODES;
    k_zero2 <<<(na + nb + TB - 1) / TB, TB>>>(rowptr, na, fill, nb);
    k_count3<<<dim3(ebl, 3), TB>>>(e0, e1, e2, rowptr);
    k_scan3 <<<3, 1024>>>(rowptr);

    // 3-5: layer-0 GEMM complex
    {
        long long totA = (long long)MPAD * 512;
        k_cvtA<<<(unsigned)((totA + TB - 1) / TB), TB>>>(x0, A2, N_NODES, F_IN, 512);
        k_cvtB<<<(3 * 128 * 512 + TB - 1) / TB, TB>>>(W0[0], W0[1], W0[2], B2, F_IN, 512, 128);
        tc_mma<512, 384, 128><<<dim3(3, rb), 256, SM0>>>(A2, B2, h, N_NODES);
    }
    // 6: finish CSR
    k_fill3<<<dim3(ebl, 3), TB>>>(e0, e1, e2, rowptr, fill, csrc);

    // layer 0 attention + mix
    k_al3 <<<nwb, TB>>>(h, 384, 64, as0[0], as0[1], as0[2], ad0[0], ad0[1], ad0[2], als, ald);
    k_gat3<<<dim3(gwb, 3), 256>>>(h, 384, 64, rowptr, csrc, als, ald,
                                  b0[0], b0[1], b0[2], st[0], st[1], st[2], 1);
    k_mix <<<(N_NODES * 128 + TB - 1) / TB, TB>>>(st[0], st[1], st[2], aggW0, aggw0,
                                                  xb, N_NODES * 128);

    // layer 1
    {
        long long totA = (long long)MPAD * 128;
        k_cvtA<<<(unsigned)((totA + TB - 1) / TB), TB>>>(xb, A2, N_NODES, 128, 128);
        k_cvtB<<<(3 * 80 * 128 + TB - 1) / TB, TB>>>(W1[0], W1[1], W1[2], B2, 128, 128, 80);
        tc_mma<128, 240, 80><<<dim3(3, rb), 256, SM1>>>(A2, B2, h, N_NODES);
    }
    k_al3 <<<nwb, TB>>>(h, 240, 40, as1[0], as1[1], as1[2], ad1[0], ad1[1], ad1[2], als, ald);
    k_gat3<<<dim3(gwb, 3), 256>>>(h, 240, 40, rowptr, csrc, als, ald,
                                  b1[0], b1[1], b1[2], st[0], st[1], st[2], 0);
    k_mix <<<(N_NODES * 40 + TB - 1) / TB, TB>>>(st[0], st[1], st[2], aggW1, aggw1,
                                                 xb, N_NODES * 40);
    k_lsm <<<nwb, TB>>>(xb, (float*)d_out);
}

// round 17
// speedup vs baseline: 1.2111x; 1.2111x over previous
#include <cuda_runtime.h>
#include <math.h>
#include <stdint.h>

#define N_NODES 50000
#define F_IN    500
#define NEDGE   800000
#define MPAD    50048            // 391 * 128

// ---------------- scratch (device globals: no allocation allowed) ----------
__device__ __align__(256) float g_h  [N_NODES * 384];   // GEMM out (L0:384, L1:240)
__device__ __align__(256) float g_als[3 * N_NODES * 2];
__device__ __align__(256) float g_ald[3 * N_NODES * 2];
__device__ __align__(256) float g_s0 [N_NODES * 128];
__device__ __align__(256) float g_s1 [N_NODES * 128];
__device__ __align__(256) float g_s2 [N_NODES * 128];
__device__ __align__(256) float g_x  [N_NODES * 128];   // mix out / logits
__device__ __align__(256) float g_B2 [384 * 512];       // transposed f32 weights [n][k]
__device__ int g_rowptr[3 * (N_NODES + 1)];
__device__ int g_csrc  [3][NEDGE];
__device__ int g_fill  [3 * N_NODES];

// ---------------- helpers ---------------------------------------------------
__device__ __forceinline__ float lrelu(float x) { return x > 0.f ? x : 0.2f * x; }
__device__ __forceinline__ float eluf (float x) { return x > 0.f ? x : expm1f(x); }

__device__ __forceinline__ uint32_t smem_to_u32(const void* p) {
    uint32_t a;
    asm("{ .reg .u64 t; cvta.to.shared.u64 t, %1; cvt.u32.u64 %0, t; }" : "=r"(a) : "l"(p));
    return a;
}
__device__ __forceinline__ float tf32_hi(float v) {
    uint32_t u;
    asm("cvt.rna.tf32.f32 %0, %1;" : "=r"(u) : "f"(v));
    return __uint_as_float(u);
}
__device__ __forceinline__ void ldsm_x4(uint32_t* r, uint32_t a) {
    asm volatile("ldmatrix.sync.aligned.m8n8.x4.shared.b16 {%0,%1,%2,%3}, [%4];"
                 : "=r"(r[0]), "=r"(r[1]), "=r"(r[2]), "=r"(r[3]) : "r"(a));
}
__device__ __forceinline__ void mma_tf32(float* c, const uint32_t* a, const uint32_t* b) {
    asm volatile("mma.sync.aligned.m16n8k8.row.col.f32.tf32.tf32.f32 "
                 "{%0,%1,%2,%3},{%4,%5,%6,%7},{%8,%9},{%0,%1,%2,%3};"
                 : "+f"(c[0]), "+f"(c[1]), "+f"(c[2]), "+f"(c[3])
                 : "r"(a[0]), "r"(a[1]), "r"(a[2]), "r"(a[3]), "r"(b[0]), "r"(b[1]));
}

// ---------------- weight transpose-pack: B2[n][k] = W_{n/Np}[k][n%Np] -------
__global__ void k_cvtBt(const float* W0, const float* W1, const float* W2,
                        float* __restrict__ B2, int K, int KHALF, int Np)
{
    int i = blockIdx.x * blockDim.x + threadIdx.x;
    int tot = 3 * Np * KHALF;
    if (i >= tot) return;
    int k = i % KHALF, n = i / KHALF;
    int o = n / Np, j = n % Np;
    const float* W = (o == 0) ? W0 : (o == 1) ? W1 : W2;
    B2[i] = (k < K) ? W[(size_t)k * Np + j] : 0.f;
}

// ---------------- tensor-core GEMM: in-register 3xTF32 ----------------------
// C[M,NTOT] = X[M,AK] @ B2^T.  Block: 128 x BN, 8 warps (4m x 2n), K chunks of
// 32 f32, double-buffered SMEM, 144B pitch. hi/lo split on fragments in regs.
template<int KHALF, int NTOT, int BN>
__global__ __launch_bounds__(256)
void tc_mma(const float* __restrict__ X, int AK,
            const float* __restrict__ B2, float* __restrict__ C, int M)
{
    constexpr int CHUNKS = KHALF / 32;
    constexpr int LDT    = 144;                // smem row pitch, bytes
    constexpr int ABY    = 128 * LDT;
    constexpr int BBY    = BN * LDT;
    constexpr int STAGE  = ABY + BBY;
    constexpr int WN     = BN / 2;
    constexpr int NF     = WN / 8;
    constexpr int NVB    = BN * 8;             // B uint4 loads per chunk
    constexpr int BB     = (NVB + 255) / 256;

    extern __shared__ char smem[];
    const uint32_t sb = smem_to_u32(smem);
    const int tid = threadIdx.x, wid = tid >> 5, l = tid & 31;
    const int bm  = blockIdx.y * 128;
    const int bng = blockIdx.x * BN;
    const int warp_m = (wid & 3) * 32;
    const int warp_n = (wid >> 2) * WN;

    float acc[2][NF][4];
#pragma unroll
    for (int mf = 0; mf < 2; ++mf)
#pragma unroll
        for (int nf = 0; nf < NF; ++nf)
#pragma unroll
            for (int j = 0; j < 4; ++j) acc[mf][nf][j] = 0.f;

    const int a_off = (warp_m + (l & 7) + ((l >> 3) & 1) * 8) * LDT + ((l >> 4) & 1) * 16;
    const int b_row_off = (warp_n + (l >> 2)) * LDT + (l & 3) * 4;

#define LOADCH(c, ra, rb)                                                            \
    {                                                                                \
        const int k0 = (c) * 32;                                                     \
        _Pragma("unroll")                                                            \
        for (int i = 0; i < 4; ++i) {                                                \
            int idx = tid + i * 256;                                                 \
            int r = idx >> 3, q = idx & 7;                                           \
            bool v = (bm + r < M) && (k0 + q * 4 < AK);                              \
            ra[i] = v ? *(const uint4*)(X + (size_t)(bm + r) * AK + k0 + q * 4)      \
                      : make_uint4(0u, 0u, 0u, 0u);                                  \
        }                                                                            \
        _Pragma("unroll")                                                            \
        for (int i = 0; i < BB; ++i) {                                               \
            int idx = tid + i * 256;                                                 \
            if ((NVB % 256 == 0) || idx < NVB) {                                     \
                int n = idx >> 3, q = idx & 7;                                       \
                rb[i] = *(const uint4*)(B2 + (size_t)(bng + n) * KHALF + k0 + q * 4);\
            }                                                                        \
        }                                                                            \
    }

#define STORECH(buf, ra, rb)                                                         \
    {                                                                                \
        char* ab = smem + (buf) * STAGE;                                             \
        char* bb = smem + (buf) * STAGE + ABY;                                       \
        _Pragma("unroll")                                                            \
        for (int i = 0; i < 4; ++i) {                                                \
            int idx = tid + i * 256;                                                 \
            int r = idx >> 3, q = idx & 7;                                           \
            *(uint4*)(ab + r * LDT + q * 16) = ra[i];                                \
        }                                                                            \
        _Pragma("unroll")                                                            \
        for (int i = 0; i < BB; ++i) {                                               \
            int idx = tid + i * 256;                                                 \
            if ((NVB % 256 == 0) || idx < NVB) {                                     \
                int n = idx >> 3, q = idx & 7;                                       \
                *(uint4*)(bb + n * LDT + q * 16) = rb[i];                            \
            }                                                                        \
        }                                                                            \
    }

#define COMPCH(buf)                                                                  \
    {                                                                                \
        const uint32_t aab = sb + (buf) * STAGE + a_off;                             \
        const uint32_t bbb = sb + (buf) * STAGE + ABY + b_row_off;                   \
        _Pragma("unroll")                                                            \
        for (int ks = 0; ks < 4; ++ks) {                                             \
            uint32_t a0[4], a1[4];                                                   \
            ldsm_x4(a0, aab + ks * 32);                                              \
            ldsm_x4(a1, aab + 16 * LDT + ks * 32);                                   \
            uint32_t a0h[4], a0l[4], a1h[4], a1l[4];                                 \
            _Pragma("unroll")                                                        \
            for (int j = 0; j < 4; ++j) {                                            \
                float v  = __uint_as_float(a0[j]);                                   \
                float hv = tf32_hi(v);                                               \
                a0h[j] = __float_as_uint(hv);                                        \
                a0l[j] = __float_as_uint(v - hv);                                    \
                v  = __uint_as_float(a1[j]);                                         \
                hv = tf32_hi(v);                                                     \
                a1h[j] = __float_as_uint(hv);                                        \
                a1l[j] = __float_as_uint(v - hv);                                    \
            }                                                                        \
            _Pragma("unroll")                                                        \
            for (int nf = 0; nf < NF; ++nf) {                                        \
                float b0, b1;                                                        \
                asm volatile("ld.shared.b32 %0, [%1];" : "=f"(b0)                    \
                             : "r"(bbb + nf * 8 * LDT + ks * 32));                   \
                asm volatile("ld.shared.b32 %0, [%1];" : "=f"(b1)                    \
                             : "r"(bbb + nf * 8 * LDT + ks * 32 + 16));              \
                float bh0 = tf32_hi(b0), bh1 = tf32_hi(b1);                          \
                uint32_t bh[2] = {__float_as_uint(bh0), __float_as_uint(bh1)};       \
                uint32_t bl[2] = {__float_as_uint(b0 - bh0), __float_as_uint(b1 - bh1)}; \
                mma_tf32(acc[0][nf], a0h, bh);                                       \
                mma_tf32(acc[1][nf], a1h, bh);                                       \
                mma_tf32(acc[0][nf], a0h, bl);                                       \
                mma_tf32(acc[1][nf], a1h, bl);                                       \
                mma_tf32(acc[0][nf], a0l, bh);                                       \
                mma_tf32(acc[1][nf], a1l, bh);                                       \
            }                                                                        \
        }                                                                            \
    }

    {
        uint4 ra[4], rb[BB];
        LOADCH(0, ra, rb);
        STORECH(0, ra, rb);
    }
    __syncthreads();
    for (int c = 1; c < CHUNKS; ++c) {
        uint4 ra[4], rb[BB];
        LOADCH(c, ra, rb);
        COMPCH((c - 1) & 1);
        STORECH(c & 1, ra, rb);
        __syncthreads();
    }
    COMPCH((CHUNKS - 1) & 1);

    // epilogue: fragment -> C
#pragma unroll
    for (int mf = 0; mf < 2; ++mf)
#pragma unroll
        for (int nf = 0; nf < NF; ++nf) {
            int r0  = bm + warp_m + mf * 16 + (l >> 2);
            int col = bng + warp_n + nf * 8 + (l & 3) * 2;
            if (r0 < M)
                *(float2*)(C + (size_t)r0 * NTOT + col) = make_float2(acc[mf][nf][0], acc[mf][nf][1]);
            int r1 = r0 + 8;
            if (r1 < M)
                *(float2*)(C + (size_t)r1 * NTOT + col) = make_float2(acc[mf][nf][2], acc[mf][nf][3]);
        }
#undef LOADCH
#undef STORECH
#undef COMPCH
}

// ---------------- fused attention logit pre-reduction over 3 orders ---------
__global__ void k_al3(const float* __restrict__ h, int RS, int C,
                      const float* as0, const float* as1, const float* as2,
                      const float* ad0, const float* ad1, const float* ad2,
                      float* __restrict__ als, float* __restrict__ ald)
{
    int w = (blockIdx.x * blockDim.x + threadIdx.x) >> 5;
    if (w >= N_NODES) return;
    int lane = threadIdx.x & 31;
    const float* row = h + (size_t)w * RS;
#pragma unroll
    for (int o = 0; o < 3; ++o) {
        const float* A_s = (o == 0) ? as0 : (o == 1) ? as1 : as2;
        const float* A_d = (o == 0) ? ad0 : (o == 1) ? ad1 : ad2;
#pragma unroll
        for (int hh = 0; hh < 2; ++hh) {
            float ss = 0.f, sd = 0.f;
            for (int c = lane; c < C; c += 32) {
                float v = row[o * 2 * C + hh * C + c];
                ss += v * __ldg(A_s + hh * C + c);
                sd += v * __ldg(A_d + hh * C + c);
            }
#pragma unroll
            for (int off = 16; off; off >>= 1) {
                ss += __shfl_xor_sync(~0u, ss, off);
                sd += __shfl_xor_sync(~0u, sd, off);
            }
            if (!lane) {
                als[o * 2 * N_NODES + w * 2 + hh] = ss;
                ald[o * 2 * N_NODES + w * 2 + hh] = sd;
            }
        }
    }
}

// ---------------- fused GAT aggregation: online softmax, batched prefetch ---
__global__ void k_gat3(const float* __restrict__ hall, int RS, int C,
                       const int* __restrict__ rowptr_all, const int* __restrict__ csrc_all,
                       const float* __restrict__ als_all, const float* __restrict__ ald_all,
                       const float* b0f, const float* b1f, const float* b2f,
                       float* o0, float* o1, float* o2, int concat)
{
    int n = (blockIdx.x * blockDim.x + threadIdx.x) >> 5;
    if (n >= N_NODES) return;
    const int o = blockIdx.y;
    const int* rowptr = rowptr_all + o * (N_NODES + 1);
    const int* csrc   = csrc_all + (size_t)o * NEDGE;
    const float* als  = als_all + o * 2 * N_NODES;
    const float* ald  = ald_all + o * 2 * N_NODES;
    const float* bias = (o == 0) ? b0f : (o == 1) ? b1f : b2f;
    float* out        = (o == 0) ? o0  : (o == 1) ? o1  : o2;
    const float* h    = hall + o * 2 * C;

    const int lane = threadIdx.x & 31;
    const int HC   = 2 * C;
    const int idx  = lane * 4;
    const bool act = idx < HC;
    const int head = (idx >= C) ? 1 : 0;

    const float adh = ald[n * 2 + head];
    float m   = lrelu(als[n * 2 + head] + adh);
    float den = 1.f;
    float4 acc = make_float4(0.f, 0.f, 0.f, 0.f);
    if (act) acc = *reinterpret_cast<const float4*>(h + (size_t)n * RS + idx);

    const int p0 = rowptr[n], p1 = rowptr[n + 1];
    for (int p = p0; p < p1; p += 8) {
        int sv[8]; float ev[8]; float4 hv[8];
#pragma unroll
        for (int i = 0; i < 8; ++i) {
            int q = p + i;
            sv[i] = csrc[q < p1 ? q : p1 - 1];
        }
#pragma unroll
        for (int i = 0; i < 8; ++i) ev[i] = als[sv[i] * 2 + head];
        if (act) {
#pragma unroll
            for (int i = 0; i < 8; ++i)
                hv[i] = *reinterpret_cast<const float4*>(h + (size_t)sv[i] * RS + idx);
        }
        const int cnt = min(8, p1 - p);
#pragma unroll
        for (int i = 0; i < 8; ++i) {
            if (i < cnt) {
                float e  = lrelu(ev[i] + adh);
                float nm = fmaxf(m, e);
                float sc = __expf(m - nm);
                float wg = __expf(e - nm);
                den = den * sc + wg;
                m = nm;
                if (act) {
                    acc.x = fmaf(acc.x, sc, wg * hv[i].x);
                    acc.y = fmaf(acc.y, sc, wg * hv[i].y);
                    acc.z = fmaf(acc.z, sc, wg * hv[i].z);
                    acc.w = fmaf(acc.w, sc, wg * hv[i].w);
                }
            }
        }
    }
    float inv = 1.f / (den + 1e-16f);
    float4 v = make_float4(acc.x * inv, acc.y * inv, acc.z * inv, acc.w * inv);

    if (concat) {
        if (act) {
            const float4 b = *reinterpret_cast<const float4*>(bias + idx);
            float4 r;
            r.x = eluf(v.x + b.x); r.y = eluf(v.y + b.y);
            r.z = eluf(v.z + b.z); r.w = eluf(v.w + b.w);
            *reinterpret_cast<float4*>(out + (size_t)n * HC + idx) = r;
        }
    } else {
        int half = C / 4;
        float ox = __shfl_down_sync(~0u, v.x, half);
        float oy = __shfl_down_sync(~0u, v.y, half);
        float oz = __shfl_down_sync(~0u, v.z, half);
        float ow = __shfl_down_sync(~0u, v.w, half);
        if (idx < C) {
            const float4 b = *reinterpret_cast<const float4*>(bias + idx);
            float4 r;
            r.x = eluf(0.5f * (v.x + ox) + b.x);
            r.y = eluf(0.5f * (v.y + oy) + b.y);
            r.z = eluf(0.5f * (v.z + oz) + b.z);
            r.w = eluf(0.5f * (v.w + ow) + b.w);
            *reinterpret_cast<float4*>(out + (size_t)n * C + idx) = r;
        }
    }
}

// ---------------- order mixing ----------------------------------------------
__global__ void k_mix(const float* __restrict__ s0, const float* __restrict__ s1,
                      const float* __restrict__ s2, const float* __restrict__ Wm,
                      const float* __restrict__ wf, float* __restrict__ out, int NC)
{
    int i = blockIdx.x * blockDim.x + threadIdx.x;
    if (i >= NC) return;
    float a = s0[i], b = s1[i], c = s2[i];
    float m0 = eluf(a * __ldg(Wm + 0) + b * __ldg(Wm + 3) + c * __ldg(Wm + 6));
    float m1 = eluf(a * __ldg(Wm + 1) + b * __ldg(Wm + 4) + c * __ldg(Wm + 7));
    float m2 = eluf(a * __ldg(Wm + 2) + b * __ldg(Wm + 5) + c * __ldg(Wm + 8));
    out[i] = m0 * __ldg(wf + 0) + m1 * __ldg(wf + 1) + m2 * __ldg(wf + 2);
}

// ---------------- row log-softmax over 40 classes ---------------------------
__global__ void k_lsm(const float* __restrict__ x, float* __restrict__ out)
{
    int n = (blockIdx.x * blockDim.x + threadIdx.x) >> 5;
    if (n >= N_NODES) return;
    int lane = threadIdx.x & 31;
    float v0 = (lane < 40)      ? x[(size_t)n * 40 + lane]      : -1e30f;
    float v1 = (lane + 32 < 40) ? x[(size_t)n * 40 + lane + 32] : -1e30f;
    float mx = fmaxf(v0, v1);
#pragma unroll
    for (int o = 16; o; o >>= 1) mx = fmaxf(mx, __shfl_xor_sync(~0u, mx, o));
    float s = 0.f;
    if (lane < 40)      s += expf(v0 - mx);
    if (lane + 32 < 40) s += expf(v1 - mx);
#pragma unroll
    for (int o = 16; o; o >>= 1) s += __shfl_xor_sync(~0u, s, o);
    float lse = logf(s) + mx;
    if (lane < 40)      out[(size_t)n * 40 + lane]      = v0 - lse;
    if (lane + 32 < 40) out[(size_t)n * 40 + lane + 32] = v1 - lse;
}

// ---------------- CSR build --------------------------------------------------
__global__ void k_zero2(int* a, int na, int* b, int nb)
{
    int i = blockIdx.x * blockDim.x + threadIdx.x;
    if (i < na) a[i] = 0;
    else if (i - na < nb) b[i - na] = 0;
}

__global__ void k_count3(const int* e0, const int* e1, const int* e2,
                         int* __restrict__ rowptr_all)
{
    int o = blockIdx.y;
    const int* ei = (o == 0) ? e0 : (o == 1) ? e1 : e2;
    int i = blockIdx.x * blockDim.x + threadIdx.x;
    if (i < NEDGE) atomicAdd(&rowptr_all[o * (N_NODES + 1) + ei[NEDGE + i] + 1], 1);
}

__global__ void k_scan3(int* __restrict__ rowptr_all)
{
    int* a = rowptr_all + blockIdx.x * (N_NODES + 1);
    const int n = N_NODES + 1;
    __shared__ int wsum[32];
    __shared__ int carry;
    int tid = threadIdx.x, lane = tid & 31, wid = tid >> 5;
    if (tid == 0) carry = 0;
    __syncthreads();
    for (int base = 0; base < n; base += 1024) {
        int i = base + tid;
        int v = (i < n) ? a[i] : 0;
#pragma unroll
        for (int off = 1; off < 32; off <<= 1) {
            int t = __shfl_up_sync(~0u, v, off);
            if (lane >= off) v += t;
        }
        if (lane == 31) wsum[wid] = v;
        __syncthreads();
        if (wid == 0) {
            int w = wsum[lane];
#pragma unroll
            for (int off = 1; off < 32; off <<= 1) {
                int t = __shfl_up_sync(~0u, w, off);
                if (lane >= off) w += t;
            }
            wsum[lane] = w;
        }
        __syncthreads();
        int add = carry + (wid ? wsum[wid - 1] : 0);
        if (i < n) a[i] = v + add;
        __syncthreads();
        if (tid == 0) carry += wsum[31];
        __syncthreads();
    }
}

__global__ void k_fill3(const int* e0, const int* e1, const int* e2,
                        const int* __restrict__ rowptr_all, int* __restrict__ fill,
                        int* __restrict__ csrc_all)
{
    int o = blockIdx.y;
    const int* ei = (o == 0) ? e0 : (o == 1) ? e1 : e2;
    int i = blockIdx.x * blockDim.x + threadIdx.x;
    if (i < NEDGE) {
        int d = ei[NEDGE + i];
        int pos = rowptr_all[o * (N_NODES + 1) + d] + atomicAdd(&fill[o * N_NODES + d], 1);
        csrc_all[(size_t)o * NEDGE + pos] = ei[i];
    }
}

// ---------------- host driver ------------------------------------------------
extern "C" void kernel_launch(void* const* d_in, const int* in_sizes, int n_in,
                              void* d_out, int out_size)
{
    (void)in_sizes; (void)n_in; (void)out_size;
    const float* x0 = (const float*)d_in[0];
    const int* e0 = (const int*)d_in[1];
    const int* e1 = (const int*)d_in[2];
    const int* e2 = (const int*)d_in[3];
    const float *W0[3], *as0[3], *ad0[3], *b0[3], *W1[3], *as1[3], *ad1[3], *b1[3];
    for (int o = 0; o < 3; ++o) {
        W0[o]  = (const float*)d_in[4  + 4 * o];
        as0[o] = (const float*)d_in[5  + 4 * o];
        ad0[o] = (const float*)d_in[6  + 4 * o];
        b0[o]  = (const float*)d_in[7  + 4 * o];
        W1[o]  = (const float*)d_in[16 + 4 * o];
        as1[o] = (const float*)d_in[17 + 4 * o];
        ad1[o] = (const float*)d_in[18 + 4 * o];
        b1[o]  = (const float*)d_in[19 + 4 * o];
    }
    const float* aggW0 = (const float*)d_in[28];
    const float* aggw0 = (const float*)d_in[29];
    const float* aggW1 = (const float*)d_in[30];
    const float* aggw1 = (const float*)d_in[31];

    float *h, *als, *ald, *st[3], *xb, *B2;
    int *rowptr, *csrc, *fill;
    {
        void* p;
        cudaGetSymbolAddress(&p, g_h);      h      = (float*)p;
        cudaGetSymbolAddress(&p, g_als);    als    = (float*)p;
        cudaGetSymbolAddress(&p, g_ald);    ald    = (float*)p;
        cudaGetSymbolAddress(&p, g_s0);     st[0]  = (float*)p;
        cudaGetSymbolAddress(&p, g_s1);     st[1]  = (float*)p;
        cudaGetSymbolAddress(&p, g_s2);     st[2]  = (float*)p;
        cudaGetSymbolAddress(&p, g_x);      xb     = (float*)p;
        cudaGetSymbolAddress(&p, g_B2);     B2     = (float*)p;
        cudaGetSymbolAddress(&p, g_rowptr); rowptr = (int*)p;
        cudaGetSymbolAddress(&p, g_csrc);   csrc   = (int*)p;
        cudaGetSymbolAddress(&p, g_fill);   fill   = (int*)p;
    }

    // smem: 2 stages of (128 + BN) rows * 144B
    const int SM0 = 2 * (128 + 128) * 144;   // 73728
    const int SM1 = 2 * (128 + 80) * 144;    // 59904
    cudaFuncSetAttribute(tc_mma<512, 384, 128>, cudaFuncAttributeMaxDynamicSharedMemorySize, SM0);
    cudaFuncSetAttribute(tc_mma<128, 240,  80>, cudaFuncAttributeMaxDynamicSharedMemorySize, SM1);

    const int TB  = 256;
    const int ebl = (NEDGE + TB - 1) / TB;
    const int nwb = (N_NODES * 32 + TB - 1) / TB;
    const int gwb = (N_NODES * 32 / 256);
    const int rb  = MPAD / 128;   // 391

    // 0-3: CSR build (complete before GEMM so launch #5 = tc_mma for ncu -s 5)
    int na = 3 * (N_NODES + 1), nb = 3 * N_NODES;
    k_zero2 <<<(na + nb + TB - 1) / TB, TB>>>(rowptr, na, fill, nb);
    k_count3<<<dim3(ebl, 3), TB>>>(e0, e1, e2, rowptr);
    k_scan3 <<<3, 1024>>>(rowptr);
    k_fill3 <<<dim3(ebl, 3), TB>>>(e0, e1, e2, rowptr, fill, csrc);

    // 4-5: layer-0 GEMM (B transpose-pack + 3xTF32 mma; A read in-kernel)
    k_cvtBt<<<(3 * 128 * 512 + TB - 1) / TB, TB>>>(W0[0], W0[1], W0[2], B2, F_IN, 512, 128);
    tc_mma<512, 384, 128><<<dim3(3, rb), 256, SM0>>>(x0, F_IN, B2, h, N_NODES);

    // layer 0 attention + mix
    k_al3 <<<nwb, TB>>>(h, 384, 64, as0[0], as0[1], as0[2], ad0[0], ad0[1], ad0[2], als, ald);
    k_gat3<<<dim3(gwb, 3), 256>>>(h, 384, 64, rowptr, csrc, als, ald,
                                  b0[0], b0[1], b0[2], st[0], st[1], st[2], 1);
    k_mix <<<(N_NODES * 128 + TB - 1) / TB, TB>>>(st[0], st[1], st[2], aggW0, aggw0,
                                                  xb, N_NODES * 128);

    // layer 1
    k_cvtBt<<<(3 * 80 * 128 + TB - 1) / TB, TB>>>(W1[0], W1[1], W1[2], B2, 128, 128, 80);
    tc_mma<128, 240, 80><<<dim3(3, rb), 256, SM1>>>(xb, 128, B2, h, N_NODES);
    k_al3 <<<nwb, TB>>>(h, 240, 40, as1[0], as1[1], as1[2], ad1[0], ad1[1], ad1[2], als, ald);
    k_gat3<<<dim3(gwb, 3), 256>>>(h, 240, 40, rowptr, csrc, als, ald,
                                  b1[0], b1[1], b1[2], st[0], st[1], st[2], 0);
    k_mix <<<(N_NODES * 40 + TB - 1) / TB, TB>>>(st[0], st[1], st[2], aggW1, aggw1,
                                                 xb, N_NODES * 40);
    k_lsm <<<nwb, TB>>>(xb, (float*)d_out);
}